// round 10
// baseline (speedup 1.0000x reference)
#include <cuda_runtime.h>

#define NB 4
#define NK 128
#define NG 128

// ---- output layout (float32, tuple flattened & concatenated) ----
#define OFF_ROIS    0
#define OFF_OBJ     2048
#define OFF_DELTAS  526336
#define OFF_RANKS   528384
#define OFF_SPATIAL 528896

// meta indexed by SOURCE proposal; one ready-flag per source (one poller each)
__device__ int  g_dest [NB * NK];
__device__ int4 g_box  [NB * NK];
__device__ int  g_ready[NB * NK];    // zero-init; each consumer resets its own

// grid = 512, block = 256 (verified round-7 launch config).
__global__ void __launch_bounds__(256) fused_kernel(
    const float* __restrict__ proposals,
    const float* __restrict__ obj_feat,
    const float* __restrict__ gt_boxes,
    const int*   __restrict__ gt_ranks,
    float*       __restrict__ out)
{
    const int bo = blockIdx.x;           // source index b*128 + p_src
    const int b  = bo >> 7;
    const int t  = threadIdx.x;

    // ---- payload load FIRST: independent of setup, overlaps everything ----
    const float4 payload = ((const float4*)obj_feat)[(size_t)bo * 256 + t];

    // ---- blocks with p_src == 0 run setup for their image ----
    // (blockIdx-uniform condition: every __syncthreads() below is reached by
    //  all 256 threads of the block)
    if ((bo & 127) == 0) {
        __shared__ float4 s_prop[NK];
        __shared__ float4 s_gt[NG];
        __shared__ float  s_bi[2][NK];   // best inter
        __shared__ float  s_bu[2][NK];   // best union
        __shared__ int    s_bj[2][NK];   // best index
        __shared__ unsigned s_mask[4];

        if (t < NK) s_prop[t]    = ((const float4*)proposals)[b * NK + t];
        else        s_gt[t - NK] = ((const float4*)gt_boxes)[b * NG + (t - NK)];
        __syncthreads();

        // division-free segmented argmax: seg = t>>7 scans 64 GTs for p = t&127
        {
            const int seg = t >> 7;
            const int p   = t & 127;
            const float4 pr = s_prop[p];
            const float ap = (pr.z - pr.x) * (pr.w - pr.y);
            float bi = -1.0f, bu = 1.0f;
            const int j0 = seg * 64;
            int bj = j0;
            #pragma unroll 8
            for (int j = j0; j < j0 + 64; j++) {
                const float4 gb = s_gt[j];
                const float dy = fminf(pr.z, gb.z) - fmaxf(pr.x, gb.x);
                const float dx = fminf(pr.w, gb.w) - fmaxf(pr.y, gb.y);
                const float inter = fmaxf(dx, 0.0f) * fmaxf(dy, 0.0f);
                const float u = ap + (gb.z - gb.x) * (gb.w - gb.y) - inter;
                // inter/u > bi/bu  <=>  inter*bu > bi*u  (u,bu > 0)
                if (inter * bu > bi * u) { bi = inter; bu = u; bj = j; }
            }
            s_bi[seg][p] = bi;
            s_bu[seg][p] = bu;
            s_bj[seg][p] = bj;
        }
        __syncthreads();

        // merge + exact winner IoU + ballot (warps 0-3 fully active)
        int pos = 0, bj = 0;
        if (t < NK) {
            float bi = s_bi[0][t], bu = s_bu[0][t];
            bj = s_bj[0][t];
            const float bi1 = s_bi[1][t], bu1 = s_bu[1][t];
            if (bi1 * bu > bi * bu1) { bi = bi1; bu = bu1; bj = s_bj[1][t]; }

            const float4 pr = s_prop[t];
            const float4 gb = s_gt[bj];
            // exact IoU for the winner (bit-matches reference threshold test)
            const float ap = (pr.z - pr.x) * (pr.w - pr.y);
            const float iy1 = fmaxf(pr.x, gb.x);
            const float ix1 = fmaxf(pr.y, gb.y);
            const float iy2 = fminf(pr.z, gb.z);
            const float ix2 = fminf(pr.w, gb.w);
            const float inter = fmaxf(ix2 - ix1, 0.0f) * fmaxf(iy2 - iy1, 0.0f);
            const float ag = (gb.z - gb.x) * (gb.w - gb.y);
            const float iou = inter / (ap + ag - inter);
            pos = (iou >= 0.5f) ? 1 : 0;

            const unsigned m = __ballot_sync(0xFFFFFFFFu, pos);
            if ((t & 31) == 0) s_mask[t >> 5] = m;
        }
        __syncthreads();   // block-level barrier

        if (t < NK) {
            const unsigned m0 = s_mask[0], m1 = s_mask[1], m2 = s_mask[2], m3 = s_mask[3];
            const int npos = __popc(m0) + __popc(m1) + __popc(m2) + __popc(m3);
            const int w = t >> 5, l = t & 31;
            const unsigned below = (l == 0) ? 0u : (s_mask[w] & ((1u << l) - 1u));
            int rank_pos = __popc(below);
            if (w > 0) rank_pos += __popc(m0);
            if (w > 1) rank_pos += __popc(m1);
            if (w > 2) rank_pos += __popc(m2);
            const int dest = pos ? rank_pos : (npos + (t - rank_pos));

            const int sbo = (b << 7) + t;
            const int dbo = (b << 7) + dest;

            const float4 pr = s_prop[t];
            const float4 gb = s_gt[bj];
            float gy1 = gb.x, gx1 = gb.y, gy2 = gb.z, gx2 = gb.w;
            if (!pos) { gy1 = gx1 = gy2 = gx2 = 0.0f; }   // roi_gt = 0 for negatives

            // ---- publish consumer-critical meta FIRST ----
            g_dest[sbo] = dest;
            {
                // integer spatial box (window transform + denorm + round-half-even)
                const float win0 = 128.0f / 1023.0f;
                const float win2 = 895.0f / 1023.0f;
                const float wsc  = win2 - win0;
                int by1 = (int)rintf(((gy1 - win0) / wsc) * 479.0f);
                int bx1 = (int)rintf(gx1 * 639.0f);
                int by2 = (int)rintf(((gy2 - win0) / wsc) * 479.0f + 1.0f);
                int bx2 = (int)rintf(gx2 * 639.0f + 1.0f);
                if (!((by2 - by1) * (bx2 - bx1) > 0)) { by1 = bx1 = by2 = bx2 = 0; }
                g_box[sbo] = make_int4(by1, bx1, by2, bx2);
            }
            // st.release orders this thread's g_dest/g_box stores before the flag
            asm volatile("st.release.gpu.global.b32 [%0], %1;"
                         :: "l"(&g_ready[sbo]), "r"(1) : "memory");

            // ---- epilogue (not consumer-critical): rois / deltas / ranks ----
            ((float4*)(out + OFF_ROIS))[dbo] = pr;
            float4 dl = make_float4(0.f, 0.f, 0.f, 0.f);
            float rk = 0.0f;
            if (pos) {
                const float h  = pr.z - pr.x, wd = pr.w - pr.y;
                const float cy = pr.x + 0.5f * h, cx = pr.y + 0.5f * wd;
                const float gh = gy2 - gy1, gw = gx2 - gx1;
                const float gcy = gy1 + 0.5f * gh, gcx = gx1 + 0.5f * gw;
                dl.x = ((gcy - cy) / h)  / 0.1f;
                dl.y = ((gcx - cx) / wd) / 0.1f;
                dl.z = logf(gh / h)  / 0.2f;
                dl.w = logf(gw / wd) / 0.2f;
                rk = (float)gt_ranks[b * NG + bj];
            }
            ((float4*)(out + OFF_DELTAS))[dbo] = dl;
            out[OFF_RANKS + dbo] = rk;
        }
    }

    // ---- handshake: exactly one poller per flag address (round-7 verified) ----
    if (t == 0) {
        int v;
        asm volatile("ld.acquire.gpu.global.b32 %0, [%1];"
                     : "=r"(v) : "l"(&g_ready[bo]) : "memory");
        while (v == 0) {
            __nanosleep(40);
            asm volatile("ld.acquire.gpu.global.b32 %0, [%1];"
                         : "=r"(v) : "l"(&g_ready[bo]) : "memory");
        }
        g_ready[bo] = 0;   // self-reset (single reader, ordered after the read)
    }
    __syncthreads();       // block-level: publishes acquire to all threads

    // ---- scatter: write payload + spatial to dest slot ----
    const int dest = g_dest[bo];
    const int4 bx  = g_box[bo];
    const int dbo  = (b << 7) + dest;

    ((float4*)(out + OFF_OBJ))[(size_t)dbo * 256 + t] = payload;

    // analytic spatial: thread t writes float4 covering elements [4t, 4t+4)
    const int row  = t >> 3;
    const int col0 = (t & 7) * 4;
    float4 v = make_float4(0.f, 0.f, 0.f, 0.f);
    if (row >= 4 && row < 28) {
        const int r1 = 20 * (row - 4) + 9;
        const float fy = (float)((bx.x < r1)     && (r1     < bx.z))
                       + (float)((bx.x < r1 + 1) && (r1 + 1 < bx.z));
        const float sc = 0.25f * fy;
        float* vv = &v.x;
        #pragma unroll
        for (int k = 0; k < 4; k++) {
            const int c1 = 20 * (col0 + k) + 9;
            const float fx = (float)((bx.y < c1)     && (c1     < bx.w))
                           + (float)((bx.y < c1 + 1) && (c1 + 1 < bx.w));
            vv[k] = sc * fx;
        }
    }
    ((float4*)(out + OFF_SPATIAL))[(size_t)dbo * 256 + t] = v;
}

extern "C" void kernel_launch(void* const* d_in, const int* in_sizes, int n_in,
                              void* d_out, int out_size)
{
    const float* proposals = (const float*)d_in[0];
    const float* obj_feat  = (const float*)d_in[1];
    const float* gt_boxes  = (const float*)d_in[2];
    const int*   gt_ranks  = (const int*)  d_in[3];
    float* out = (float*)d_out;

    fused_kernel<<<NB * NK, 256>>>(proposals, obj_feat, gt_boxes, gt_ranks, out);
}